// round 7
// baseline (speedup 1.0000x reference)
#include <cuda_runtime.h>
#include <cstdint>

#define B_SZ   256
#define F_SZ   128
#define DEPTHD 6
#define C_SZ   100
#define L_SZ   64
#define NTREE  8192
#define KTOT   ((size_t)NTREE * L_SZ)     /* 524288 */
#define NSLICE 148                        /* one CTA per tree-slice */
#define N_PAD  104                        /* C padded: 13 n-tiles of 8 */
#define SST    68                         /* sel smem stride (words), 68 mod 32 = 4 */
#define HST2   68                         /* accum stride: 2 trees x 32 words + 4 pad */
#define W_SCALE   512.0f
#define W_INV     0.001953125f            /* 1/512 */

/* scratch: fv[m = tree*6+d][b], 49152 x 256 floats = 50.3 MB */
__device__ float g_fv[NTREE * DEPTHD * B_SZ];

/* ---- helpers ---- */
/* pack (lo, hi) floats -> f16x2 reg. PTX: cvt d, a, b => d.lo = b, d.hi = a */
__device__ __forceinline__ uint32_t f2h2(float lo, float hi) {
    uint32_t u; asm("cvt.rn.f16x2.f32 %0, %1, %2;" : "=r"(u) : "f"(hi), "f"(lo)); return u;
}
__device__ __forceinline__ void mma16(float c[4],
                                      uint32_t a0, uint32_t a1, uint32_t a2, uint32_t a3,
                                      uint32_t b0, uint32_t b1) {
    asm volatile(
        "mma.sync.aligned.m16n8k16.row.col.f32.f16.f16.f32 "
        "{%0,%1,%2,%3}, {%4,%5,%6,%7}, {%8,%9}, {%0,%1,%2,%3};"
        : "+f"(c[0]), "+f"(c[1]), "+f"(c[2]), "+f"(c[3])
        : "r"(a0), "r"(a1), "r"(a2), "r"(a3), "r"(b0), "r"(b1));
}

/* ================= kernel 1: selector GEMM + sigmoid (fp16 m16n8k16) ========= */
__global__ void __launch_bounds__(256) sel_fp16(const float* __restrict__ x,
                                                const float* __restrict__ selW,
                                                const float* __restrict__ selb) {
    extern __shared__ uint32_t sm[];
    uint32_t* As = sm;                 /* 128 x SST */
    uint32_t* Bs = sm + 128 * SST;     /* 64 x SST  */

    const int tid = threadIdx.x;
    const int wid = tid >> 5, lane = tid & 31;
    const int g = lane >> 2, tg = lane & 3;
    const int mw = wid & 3, nw = wid >> 2;
    const int row0 = blockIdx.x * 128, col0 = blockIdx.y * 64;

#pragma unroll
    for (int it = 0; it < 16; it++) {
        int e = tid + it * 256;
        int r = e >> 5, q = e & 31;
        float4 v = *(const float4*)(selW + (size_t)(row0 + r) * F_SZ + q * 4);
        uint2 w; w.x = f2h2(v.x, v.y); w.y = f2h2(v.z, v.w);
        *(uint2*)&As[r * SST + q * 2] = w;
    }
#pragma unroll
    for (int it = 0; it < 8; it++) {
        int e = tid + it * 256;
        int r = e >> 5, q = e & 31;
        float4 v = *(const float4*)(x + (size_t)(col0 + r) * F_SZ + q * 4);
        uint2 w; w.x = f2h2(v.x, v.y); w.y = f2h2(v.z, v.w);
        *(uint2*)&Bs[r * SST + q * 2] = w;
    }
    __syncthreads();

    float acc[2][4][4];
#pragma unroll
    for (int mi = 0; mi < 2; mi++)
#pragma unroll
        for (int ni = 0; ni < 4; ni++)
#pragma unroll
            for (int q = 0; q < 4; q++) acc[mi][ni][q] = 0.f;

#pragma unroll
    for (int c = 0; c < 8; c++) {
        uint32_t a[2][4], b[4][2];
#pragma unroll
        for (int mi = 0; mi < 2; mi++) {
            int mb = mw * 32 + mi * 16;
            a[mi][0] = As[(mb + g) * SST + 8 * c + tg];
            a[mi][1] = As[(mb + g + 8) * SST + 8 * c + tg];
            a[mi][2] = As[(mb + g) * SST + 8 * c + tg + 4];
            a[mi][3] = As[(mb + g + 8) * SST + 8 * c + tg + 4];
        }
#pragma unroll
        for (int ni = 0; ni < 4; ni++) {
            int nb = nw * 32 + ni * 8 + g;
            b[ni][0] = Bs[nb * SST + 8 * c + tg];
            b[ni][1] = Bs[nb * SST + 8 * c + tg + 4];
        }
#pragma unroll
        for (int mi = 0; mi < 2; mi++)
#pragma unroll
            for (int ni = 0; ni < 4; ni++)
                mma16(acc[mi][ni], a[mi][0], a[mi][1], a[mi][2], a[mi][3],
                      b[ni][0], b[ni][1]);
    }

#pragma unroll
    for (int mi = 0; mi < 2; mi++) {
        int m = row0 + mw * 32 + mi * 16 + g;
        float b0 = selb[m], b1 = selb[m + 8];
#pragma unroll
        for (int ni = 0; ni < 4; ni++) {
            int bcol = col0 + nw * 32 + ni * 8 + tg * 2;
            float2 v0, v1;
            v0.x = 1.f / (1.f + __expf(-(acc[mi][ni][0] + b0)));
            v0.y = 1.f / (1.f + __expf(-(acc[mi][ni][1] + b0)));
            v1.x = 1.f / (1.f + __expf(-(acc[mi][ni][2] + b1)));
            v1.y = 1.f / (1.f + __expf(-(acc[mi][ni][3] + b1)));
            *(float2*)&g_fv[(size_t)m * B_SZ + bcol] = v0;
            *(float2*)&g_fv[(size_t)(m + 8) * B_SZ + bcol] = v1;
        }
    }
}

/* ================= kernel 2: fused leaf + fp16 GEMM, 2 trees/iter ===========
 * grid = 148 CTAs, 512 threads, 1 CTA/SM. K=128 per iteration (2 trees).
 * A = leaf[256 b, 2x64 l] fp16, stride HST2=68; B = 512*W[104 c, 2x64 l].
 * 16 warps = 8 mw x 2 nw; warp = 2 m-tiles x {7,6} n-tiles x 8 k-chunks. */
__device__ __forceinline__ void stage_pair(uint32_t* Ab, uint32_t* Bb, int t, int t1,
                                           const float* __restrict__ outW,
                                           int tid, int b_local, int lh) {
    /* ---- leaf tiles for trees t, t+1 (zero-fill past t1) ---- */
#pragma unroll
    for (int tr = 0; tr < 2; tr++) {
        uint32_t* dst = Ab + b_local * HST2 + tr * 32 + lh * 16;
        if (t + tr < t1) {
            const float* fp = g_fv + (size_t)(t + tr) * (DEPTHD * B_SZ) + b_local;
            float p0 = fp[0], p1 = fp[256], p2 = fp[512];
            float p3 = fp[768], p4 = fp[1024], p5 = fp[1280];
            float g0 = lh ? (1.f - p0) : p0;
            float a1[2], a2[4], a3[8], a4[16];
            a1[0] = g0 * p1; a1[1] = g0 * (1.f - p1);
#pragma unroll
            for (int i = 0; i < 2; i++) { a2[2*i] = a1[i] * p2; a2[2*i+1] = a1[i] * (1.f - p2); }
#pragma unroll
            for (int i = 0; i < 4; i++) { a3[2*i] = a2[i] * p3; a3[2*i+1] = a2[i] * (1.f - p3); }
#pragma unroll
            for (int i = 0; i < 8; i++) { a4[2*i] = a3[i] * p4; a4[2*i+1] = a3[i] * (1.f - p4); }
            float q5 = 1.f - p5;
#pragma unroll
            for (int i = 0; i < 4; i++) {
                uint4 w;
                w.x = f2h2(a4[4*i]     * p5, a4[4*i]     * q5);
                w.y = f2h2(a4[4*i + 1] * p5, a4[4*i + 1] * q5);
                w.z = f2h2(a4[4*i + 2] * p5, a4[4*i + 2] * q5);
                w.w = f2h2(a4[4*i + 3] * p5, a4[4*i + 3] * q5);
                *(uint4*)(dst + i * 4) = w;
            }
        } else {
            uint4 z = make_uint4(0u, 0u, 0u, 0u);
#pragma unroll
            for (int i = 0; i < 4; i++) *(uint4*)(dst + i * 4) = z;
        }
    }
    /* ---- W tiles: 104 c x 2 trees x 16 float4 = 3328 elems ---- */
#pragma unroll
    for (int it = 0; it < 7; it++) {
        int e = tid + it * 512;
        if (e < N_PAD * 32) {
            int c = e >> 5, w = e & 31;
            int tr = w >> 4, q = w & 15;
            uint2 v; v.x = 0u; v.y = 0u;
            if (c < C_SZ && t + tr < t1) {
                float4 f = *(const float4*)(outW + (size_t)c * KTOT + (size_t)(t + tr) * L_SZ + q * 4);
                v.x = f2h2(f.x * W_SCALE, f.y * W_SCALE);
                v.y = f2h2(f.z * W_SCALE, f.w * W_SCALE);
            }
            *(uint2*)&Bb[c * HST2 + tr * 32 + q * 2] = v;
        }
    }
}

template <int NT>
__device__ __forceinline__ void mma_pair(float acc[2][7][4],
                                         const uint32_t* __restrict__ As,
                                         const uint32_t* __restrict__ Bs,
                                         int mw, int nw, int g, int tg) {
#pragma unroll
    for (int c = 0; c < 8; c++) {
        uint32_t a[2][4], b[NT][2];
#pragma unroll
        for (int mi = 0; mi < 2; mi++) {
            int mb = mw * 32 + mi * 16;
            a[mi][0] = As[(mb + g) * HST2 + 8 * c + tg];
            a[mi][1] = As[(mb + g + 8) * HST2 + 8 * c + tg];
            a[mi][2] = As[(mb + g) * HST2 + 8 * c + tg + 4];
            a[mi][3] = As[(mb + g + 8) * HST2 + 8 * c + tg + 4];
        }
#pragma unroll
        for (int ni = 0; ni < NT; ni++) {
            int nb = nw * 56 + ni * 8 + g;
            b[ni][0] = Bs[nb * HST2 + 8 * c + tg];
            b[ni][1] = Bs[nb * HST2 + 8 * c + tg + 4];
        }
#pragma unroll
        for (int mi = 0; mi < 2; mi++)
#pragma unroll
            for (int ni = 0; ni < NT; ni++)
                mma16(acc[mi][ni], a[mi][0], a[mi][1], a[mi][2], a[mi][3],
                      b[ni][0], b[ni][1]);
    }
}

__global__ void __launch_bounds__(512, 1) accum_512(const float* __restrict__ outW,
                                                    const float* __restrict__ outb,
                                                    float* __restrict__ out) {
    extern __shared__ uint32_t sm[];
    uint32_t* A0 = sm;                        /* 256*HST2 words */
    uint32_t* A1 = A0 + 256 * HST2;
    uint32_t* B0 = A1 + 256 * HST2;           /* 104*HST2 words */
    uint32_t* B1 = B0 + N_PAD * HST2;

    const int tid = threadIdx.x;
    const int wid = tid >> 5, lane = tid & 31;
    const int g = lane >> 2, tg = lane & 3;
    const int mw = wid & 7, nw = wid >> 3;
    const int slice = blockIdx.x;
    const int t0 = (slice * NTREE) / NSLICE;
    const int t1 = ((slice + 1) * NTREE) / NSLICE;

    const int b_local = tid >> 1;
    const int lh = tid & 1;

    float acc[2][7][4];
#pragma unroll
    for (int mi = 0; mi < 2; mi++)
#pragma unroll
        for (int ni = 0; ni < 7; ni++)
#pragma unroll
            for (int q = 0; q < 4; q++) acc[mi][ni][q] = 0.f;

    const int np = (t1 - t0 + 1) >> 1;
    stage_pair(A0, B0, t0, t1, outW, tid, b_local, lh);
    __syncthreads();

    for (int p = 0; p < np; p++) {
        const int buf = p & 1;
        if (p + 1 < np)
            stage_pair(buf ? A0 : A1, buf ? B0 : B1, t0 + 2 * (p + 1), t1,
                       outW, tid, b_local, lh);

        const uint32_t* As = buf ? A1 : A0;
        const uint32_t* Bs = buf ? B1 : B0;
        if (nw == 0) mma_pair<7>(acc, As, Bs, mw, nw, g, tg);
        else         mma_pair<6>(acc, As, Bs, mw, nw, g, tg);
        __syncthreads();
    }

    /* epilogue: atomicAdd (undo x512 W scale); CTA 0 also adds the bias */
    const int ntiles = nw ? 6 : 7;
    const bool addb = (blockIdx.x == 0);
#pragma unroll
    for (int mi = 0; mi < 2; mi++) {
        int row = mw * 32 + mi * 16 + g;
        float* op0 = out + (size_t)row * C_SZ;
        float* op1 = out + (size_t)(row + 8) * C_SZ;
#pragma unroll
        for (int ni = 0; ni < 7; ni++) {
            if (ni >= ntiles) break;
            int col = nw * 56 + ni * 8 + tg * 2;
            if (col < C_SZ) {
                float bb = addb ? outb[col] : 0.f;
                atomicAdd(op0 + col, acc[mi][ni][0] * W_INV + bb);
                atomicAdd(op1 + col, acc[mi][ni][2] * W_INV + bb);
            }
            if (col + 1 < C_SZ) {
                float bb = addb ? outb[col + 1] : 0.f;
                atomicAdd(op0 + col + 1, acc[mi][ni][1] * W_INV + bb);
                atomicAdd(op1 + col + 1, acc[mi][ni][3] * W_INV + bb);
            }
        }
    }
}

extern "C" void kernel_launch(void* const* d_in, const int* in_sizes, int n_in,
                              void* d_out, int out_size) {
    const float* x    = (const float*)d_in[0];
    const float* selW = (const float*)d_in[1];
    const float* selb = (const float*)d_in[2];
    const float* outW = (const float*)d_in[3];
    const float* outb = (const float*)d_in[4];
    float* out = (float*)d_out;

    cudaMemsetAsync(out, 0, (size_t)out_size * sizeof(float));

    size_t sel_smem = (size_t)(128 + 64) * SST * 4;                  /* 52224 B */
    cudaFuncSetAttribute(sel_fp16, cudaFuncAttributeMaxDynamicSharedMemorySize, (int)sel_smem);
    dim3 g1(384, 4);
    sel_fp16<<<g1, 256, sel_smem>>>(x, selW, selb);

    size_t acc_smem = (size_t)(2 * 256 + 2 * N_PAD) * HST2 * 4;      /* 195840 B */
    cudaFuncSetAttribute(accum_512, cudaFuncAttributeMaxDynamicSharedMemorySize, (int)acc_smem);
    accum_512<<<NSLICE, 512, acc_smem>>>(outW, outb, out);
}